// round 8
// baseline (speedup 1.0000x reference)
#include <cuda_runtime.h>
#include <cuda_bf16.h>
#include <cstdint>
#include <math.h>

// ================= scratch (device globals: no allocation allowed) =================
__device__ __align__(16) float g_zT [2000 * 64];
__device__ __align__(16) float g_b1T[200 * 64];
__device__ __align__(16) float g_b2T[100 * 64];
__device__ __align__(16) float g_latT[10 * 64];
__device__ __align__(16) float g_b3T[100 * 64];
__device__ __align__(16) float g_b4T[200 * 64];
__device__ __align__(16) float g_p1[3 * 200 * 64];
__device__ __align__(16) float g_p2[2 * 200 * 64];
// h B-fragments: [side][wn][lane][8 x uint4]  (words 0..15 = hi, 16..31 = lo)
__device__ __align__(16) uint4 g_frag[2][4][32][8];

// ================= helpers =================
__device__ __forceinline__ uint32_t smem_u32(const void* p) {
    uint32_t a;
    asm("{ .reg .u64 t; cvta.to.shared.u64 t, %1; cvt.u32.u64 %0, t; }" : "=r"(a) : "l"(p));
    return a;
}
__device__ __forceinline__ void ldsm_x4(uint32_t* r, uint32_t addr) {
    asm volatile("ldmatrix.sync.aligned.m8n8.x4.shared.b16 {%0,%1,%2,%3}, [%4];"
        : "=r"(r[0]), "=r"(r[1]), "=r"(r[2]), "=r"(r[3]) : "r"(addr));
}
__device__ __forceinline__ void ldsm_x2(uint32_t* r, uint32_t addr) {
    asm volatile("ldmatrix.sync.aligned.m8n8.x2.shared.b16 {%0,%1}, [%2];"
        : "=r"(r[0]), "=r"(r[1]) : "r"(addr));
}
__device__ __forceinline__ void mma_bf16(float* d, const uint32_t* a, const uint32_t* b) {
    asm volatile("mma.sync.aligned.m16n8k16.row.col.f32.bf16.bf16.f32 "
        "{%0,%1,%2,%3}, {%4,%5,%6,%7}, {%8,%9}, {%0,%1,%2,%3};"
        : "+f"(d[0]), "+f"(d[1]), "+f"(d[2]), "+f"(d[3])
        : "r"(a[0]), "r"(a[1]), "r"(a[2]), "r"(a[3]), "r"(b[0]), "r"(b[1]));
}
// pack hi16 halves of (a,b) -> bf16x2 (truncating split)
__device__ __forceinline__ uint32_t prmt_hi(float a, float b) {
    uint32_t r;
    asm("prmt.b32 %0, %1, %2, 0x7632;"
        : "=r"(r) : "r"(__float_as_uint(a)), "r"(__float_as_uint(b)));
    return r;
}
// residual after truncating hi split, packed bf16x2
__device__ __forceinline__ uint32_t pack_lo_resid(float a, float b) {
    float la = a - __uint_as_float(__float_as_uint(a) & 0xffff0000u);
    float lb = b - __uint_as_float(__float_as_uint(b) & 0xffff0000u);
    uint32_t r;
    asm("cvt.rn.bf16x2.f32 %0, %1, %2;" : "=r"(r) : "f"(lb), "f"(la));
    return r;
}

// ================= hypernet (blocks 0,1: h + B-fragments) + z transpose (blocks 2..) ====
__global__ __launch_bounds__(256) void hyper_tr(
    const float* __restrict__ mu,
    const float* __restrict__ enW0, const float* __restrict__ enb0,
    const float* __restrict__ enW1, const float* __restrict__ enb1,
    const float* __restrict__ deW0, const float* __restrict__ deb0,
    const float* __restrict__ deW1, const float* __restrict__ deb1,
    const float* __restrict__ z)
{
    int tid = threadIdx.x;
    if (blockIdx.x >= 2) {
        int idx = (blockIdx.x - 2) * 256 + tid;
        if (idx < 2000 * 64) {
            int i = idx >> 6, b = idx & 63;
            g_zT[idx] = z[b * 2000 + i];
        }
        return;
    }
    const int side = blockIdx.x;
    const float* W0; const float* b0; const float* W1; const float* b1;
    if (side == 0) { W0 = enW0; b0 = enb0; W1 = enW1; b1 = enb1; }
    else           { W0 = deW0; b0 = deb0; W1 = deW1; b1 = deb1; }

    __shared__ float mus[256];
    __shared__ float h1[64][65];
    __shared__ __align__(16) __nv_bfloat16 hsH[64 * 72];
    __shared__ __align__(16) __nv_bfloat16 hsL[64 * 72];

    mus[tid] = mu[tid];
    __syncthreads();
    for (int idx = tid; idx < 4096; idx += 256) {
        int b = idx >> 6, o = idx & 63;
        float s = b0[o];
#pragma unroll
        for (int j = 0; j < 4; j++) s += mus[b * 4 + j] * W0[o * 4 + j];
        h1[b][o] = tanhf(s);
    }
    __syncthreads();
    for (int idx = tid; idx < 4096; idx += 256) {
        int b = idx >> 6, o = idx & 63;
        float s = b1[o];
#pragma unroll
        for (int k = 0; k < 64; k++) s += h1[b][k] * W1[o * 64 + k];
        float f = tanhf(s);
        __nv_bfloat16 hi = __float2bfloat16_rn(f);
        __nv_bfloat16 lo = __float2bfloat16_rn(f - __bfloat162float(hi));
        hsH[b * 72 + o] = hi;
        hsL[b * 72 + o] = lo;
    }
    __syncthreads();

    // warps 0..3: build B fragments exactly as hfc consumers would, store to gmem
    int wid = tid >> 5, lane = tid & 31;
    if (wid < 4) {
        const int wn = wid;
        const uint32_t smbH = smem_u32(hsH), smbL = smem_u32(hsL);
        uint32_t w_[32];
        int l2 = lane & 15, rr = l2 & 7, rs = l2 >> 3;
#pragma unroll
        for (int nt = 0; nt < 2; nt++) {
            int bb = wn * 16 + nt * 8 + rr;
#pragma unroll
            for (int ks = 0; ks < 4; ks++) {
                uint32_t o_ = (uint32_t)(bb * 144 + ks * 32 + rs * 16);
                uint32_t th[2], tl[2];
                ldsm_x2(th, smbH + o_);
                ldsm_x2(tl, smbL + o_);
                w_[nt * 8 + ks * 2 + 0] = th[0];
                w_[nt * 8 + ks * 2 + 1] = th[1];
                w_[16 + nt * 8 + ks * 2 + 0] = tl[0];
                w_[16 + nt * 8 + ks * 2 + 1] = tl[1];
            }
        }
#pragma unroll
        for (int j = 0; j < 8; j++)
            g_frag[side][wn][lane][j] = make_uint4(w_[4*j], w_[4*j+1], w_[4*j+2], w_[4*j+3]);
    }
}

// ================= split reduce (+opt tanh, +opt row-major copy) =================
__global__ void reduce_kernel(const float* __restrict__ part, float* __restrict__ outT,
                              float* __restrict__ out, int ostride, int n, int s, int do_tanh)
{
    int i = blockIdx.x * 256 + threadIdx.x;
    if (i < n) {
        float v = 0.f;
        for (int j = 0; j < s; j++) v += part[(long)j * n + i];
        if (do_tanh) v = tanhf(v);
        if (outT) outT[i] = v;
        if (out) { int c = i >> 6, b = i & 63; out[b * ostride + c] = v; }
    }
}

// ================= fused hyper-FC: team-staged HMMA =================
// Block = 256 thr = 2 teams x 4 warps. Team owns channel cc = grp*2+team in K-split.
// Per 16-row tile: D[j,b] = Wrows @ h^T (3-term bf16 split, fp32 acc);
//                  acc[b] += (D[j,b] + b2[j]) * x'[j,b]   (x'[ni]=1 folds layer bias).
__global__ void __launch_bounds__(256) hfc(
    const float* __restrict__ W2, const float* __restrict__ b2,
    const float* __restrict__ xT, const uint4* __restrict__ hfrag,
    float* __restrict__ part_out,
    float* __restrict__ outT, float* __restrict__ out, int ostride, int do_tanh,
    int ni, int no, long off, int nsplit)
{
    __shared__ __align__(16) char wt[2][2 * 4608];   // team, stage x {hi(2304), lo(2304)}
    __shared__ float b2s[2][2][16];

    const int tid = threadIdx.x, lane = tid & 31, wid = tid >> 5;
    const int team = wid >> 2, wn = wid & 3, tt = tid & 127;
    const int grp = blockIdx.x / nsplit, split = blockIdx.x % nsplit;
    const int cc = grp * 2 + team;
    const int K1 = ni + 1;
    const int ilen = (K1 + nsplit - 1) / nsplit;
    const int ibeg = split * ilen;
    const int iend = min(ibeg + ilen, K1);
    const int ntiles = (iend - ibeg + 15) >> 4;

    // ---- B fragments: 8 coalesced LDG.128, no smem, no block sync ----
    uint32_t bh[2][4][2], bl[2][4][2];
    {
        const uint4* fp = hfrag + (wn * 32 + lane) * 8;
        uint32_t w_[32];
#pragma unroll
        for (int j = 0; j < 8; j++) {
            uint4 v = fp[j];
            w_[4*j] = v.x; w_[4*j+1] = v.y; w_[4*j+2] = v.z; w_[4*j+3] = v.w;
        }
#pragma unroll
        for (int nt = 0; nt < 2; nt++)
#pragma unroll
        for (int ks = 0; ks < 4; ks++)
#pragma unroll
        for (int r = 0; r < 2; r++) {
            bh[nt][ks][r] = w_[nt * 8 + ks * 2 + r];
            bl[nt][ks][r] = w_[16 + nt * 8 + ks * 2 + r];
        }
    }

    const long wbase = off + (long)cc * ni;
    const long brow  = off + (long)ni * no + cc;
    const int sr = tt >> 3, sq = tt & 7;            // stage mapping: row 0..15, col8 0..7
    const uint32_t wtb = smem_u32(wt[team]);
    const int barid = 1 + team;

    float4 pwa, pwb; float pb2;
    auto ldg_tile = [&](int i0) {
        int gi = i0 + sr;
        bool valid = gi < iend;
        long row = (gi < ni) ? (wbase + gi) : brow;
        const float4 f40 = make_float4(0.f, 0.f, 0.f, 0.f);
        pwa = valid ? *(const float4*)(W2 + row * 64 + sq * 8)     : f40;
        pwb = valid ? *(const float4*)(W2 + row * 64 + sq * 8 + 4) : f40;
        pb2 = (valid && sq == 0) ? b2[row] : 0.f;
    };
    auto sts_tile = [&](int sbuf) {
        char* ph = wt[team] + sbuf * 4608 + sr * 144 + sq * 16;
        uint4 H, L;
        H.x = prmt_hi(pwa.x, pwa.y); H.y = prmt_hi(pwa.z, pwa.w);
        H.z = prmt_hi(pwb.x, pwb.y); H.w = prmt_hi(pwb.z, pwb.w);
        L.x = pack_lo_resid(pwa.x, pwa.y); L.y = pack_lo_resid(pwa.z, pwa.w);
        L.z = pack_lo_resid(pwb.x, pwb.y); L.w = pack_lo_resid(pwb.z, pwb.w);
        *(uint4*)ph = H;
        *(uint4*)(ph + 2304) = L;
        if (sq == 0) b2s[team][sbuf][sr] = pb2;
    };

    ldg_tile(ibeg);
    sts_tile(0);

    float acc[4] = {0.f, 0.f, 0.f, 0.f};
    const float2 z2 = make_float2(0.f, 0.f);
    int buf = 0;

    for (int mt = 0; mt < ntiles; ++mt) {
        if (mt + 1 < ntiles) ldg_tile(ibeg + (mt + 1) * 16);   // prefetch into regs
        asm volatile("bar.sync %0, 128;" :: "r"(barid) : "memory");

        // ---- x loads ----
        const int g0 = ibeg + mt * 16 + (lane >> 2);
        const int g1 = g0 + 8;
        const bool v0 = g0 < iend, v1 = g1 < iend;
        float2 x0[2], x1[2];
#pragma unroll
        for (int nt = 0; nt < 2; nt++) {
            int col = wn * 16 + nt * 8 + (lane & 3) * 2;
            x0[nt] = v0 ? (g0 < ni ? *(const float2*)(xT + (long)g0 * 64 + col) : make_float2(1.f, 1.f)) : z2;
            x1[nt] = v1 ? (g1 < ni ? *(const float2*)(xT + (long)g1 * 64 + col) : make_float2(1.f, 1.f)) : z2;
        }

        // ---- A fragments via ldmatrix ----
        uint32_t aH[4][4], aL[4][4];
        {
            int lrow = (lane & 7) + ((lane >> 3) & 1) * 8;
            int kh = lane >> 4;
            uint32_t base = wtb + buf * 4608 + (uint32_t)(lrow * 144 + kh * 16);
#pragma unroll
            for (int ks = 0; ks < 4; ks++) {
                ldsm_x4(aH[ks], base + ks * 32);
                ldsm_x4(aL[ks], base + 2304 + ks * 32);
            }
        }

        // ---- MMA (3-term split) ----
        float d[2][4] = {{0.f,0.f,0.f,0.f},{0.f,0.f,0.f,0.f}};
#pragma unroll
        for (int ks = 0; ks < 4; ks++) {
#pragma unroll
            for (int nt = 0; nt < 2; nt++) {
                mma_bf16(d[nt], aH[ks], bh[nt][ks]);
                mma_bf16(d[nt], aH[ks], bl[nt][ks]);
                mma_bf16(d[nt], aL[ks], bh[nt][ks]);
            }
        }

        // ---- fold with bias + x ----
        const float bb0 = b2s[team][buf][lane >> 2];
        const float bb1 = b2s[team][buf][(lane >> 2) + 8];
#pragma unroll
        for (int nt = 0; nt < 2; nt++) {
            acc[nt * 2 + 0] += (d[nt][0] + bb0) * x0[nt].x + (d[nt][2] + bb1) * x1[nt].x;
            acc[nt * 2 + 1] += (d[nt][1] + bb0) * x0[nt].y + (d[nt][3] + bb1) * x1[nt].y;
        }

        if (mt + 1 < ntiles) sts_tile(buf ^ 1);
        buf ^= 1;
    }

    // ---- reduce over j-groups (lane bits 2..4) and write ----
#pragma unroll
    for (int e = 0; e < 4; e++) {
        acc[e] += __shfl_xor_sync(0xffffffffu, acc[e], 4);
        acc[e] += __shfl_xor_sync(0xffffffffu, acc[e], 8);
        acc[e] += __shfl_xor_sync(0xffffffffu, acc[e], 16);
    }
    if (lane < 4) {
#pragma unroll
        for (int nt = 0; nt < 2; nt++)
#pragma unroll
        for (int e2 = 0; e2 < 2; e2++) {
            int col = wn * 16 + nt * 8 + lane * 2 + e2;
            float v = acc[nt * 2 + e2];
            if (part_out) {
                part_out[(long)split * (no * 64) + (long)cc * 64 + col] = v;
            } else {
                if (do_tanh) v = tanhf(v);
                if (outT) outT[(long)cc * 64 + col] = v;
                if (out)  out[(long)col * ostride + cc] = v;
            }
        }
    }
}

extern "C" void kernel_launch(void* const* d_in, const int* in_sizes, int n_in,
                              void* d_out, int out_size)
{
    const float* z    = (const float*)d_in[0];
    const float* mu   = (const float*)d_in[1];
    const float* enW0 = (const float*)d_in[2];
    const float* enb0 = (const float*)d_in[3];
    const float* enW1 = (const float*)d_in[4];
    const float* enb1 = (const float*)d_in[5];
    const float* enW2 = (const float*)d_in[6];
    const float* enb2 = (const float*)d_in[7];
    const float* deW0 = (const float*)d_in[8];
    const float* deb0 = (const float*)d_in[9];
    const float* deW1 = (const float*)d_in[10];
    const float* deb1 = (const float*)d_in[11];
    const float* deW2 = (const float*)d_in[12];
    const float* deb2 = (const float*)d_in[13];
    float* out = (float*)d_out;

    float *zT, *b1T, *b2T, *latT, *b3T, *b4T, *p1, *p2;
    uint4* frag;
    cudaGetSymbolAddress((void**)&zT,   g_zT);
    cudaGetSymbolAddress((void**)&b1T,  g_b1T);
    cudaGetSymbolAddress((void**)&b2T,  g_b2T);
    cudaGetSymbolAddress((void**)&latT, g_latT);
    cudaGetSymbolAddress((void**)&b3T,  g_b3T);
    cudaGetSymbolAddress((void**)&b4T,  g_b4T);
    cudaGetSymbolAddress((void**)&p1,   g_p1);
    cudaGetSymbolAddress((void**)&p2,   g_p2);
    cudaGetSymbolAddress((void**)&frag, g_frag);

    const uint4* fragEn = frag;
    const uint4* fragDe = frag + 4 * 32 * 8;

    // hypernet hidden states (+B fragments) + z transpose
    hyper_tr<<<502, 256>>>(mu, enW0, enb0, enW1, enb1, deW0, deb0, deW1, deb1, z);

    // encoder L0: 2000->200 linear, 3 K-splits (grid 300)
    hfc<<<300, 256>>>(enW2, enb2, zT, fragEn, p1, nullptr, nullptr, 0, 0,
                      2000, 200, 0L, 3);
    reduce_kernel<<<50, 256>>>(p1, b1T, nullptr, 0, 12800, 3, 0);
    // encoder L1: 200->100, 2 splits (grid 100), tanh in reduce
    hfc<<<100, 256>>>(enW2, enb2, b1T, fragEn, p2, nullptr, nullptr, 0, 0,
                      200, 100, 400200L, 2);
    reduce_kernel<<<25, 256>>>(p2, b2T, nullptr, 0, 6400, 2, 1);
    // encoder L2: 100->10, 2 splits (grid 10); reduce -> latT + latent tail of d_out
    hfc<<<10, 256>>>(enW2, enb2, b2T, fragEn, p1, nullptr, nullptr, 0, 0,
                     100, 10, 420300L, 2);
    reduce_kernel<<<3, 256>>>(p1, latT, out + 128000, 10, 640, 2, 0);

    // decoder L0: 10->100 linear, direct transposed write (grid 50)
    hfc<<<50, 256>>>(deW2, deb2, latT, fragDe, nullptr, b3T, nullptr, 0, 0,
                     10, 100, 0L, 1);
    // decoder L1: 100->200, tanh, direct transposed write (grid 100)
    hfc<<<100, 256>>>(deW2, deb2, b3T, fragDe, nullptr, b4T, nullptr, 0, 1,
                      100, 200, 1100L, 1);
    // decoder L2: 200->2000 linear, straight to d_out row-major (grid 1000)
    hfc<<<1000, 256>>>(deW2, deb2, b4T, fragDe, nullptr, nullptr, out, 2000, 0,
                       200, 2000, 21300L, 1);
}

// round 9
// speedup vs baseline: 1.0134x; 1.0134x over previous
#include <cuda_runtime.h>
#include <cuda_bf16.h>
#include <cstdint>
#include <math.h>

// ================= scratch (device globals: no allocation allowed) =================
__device__ __align__(16) float g_zT [2000 * 64];
__device__ __align__(16) float g_b1T[200 * 64];
__device__ __align__(16) float g_b2T[100 * 64];
__device__ __align__(16) float g_latT[10 * 64];
__device__ __align__(16) float g_b3T[100 * 64];
__device__ __align__(16) float g_b4T[200 * 64];
__device__ __align__(16) float g_p1[3 * 200 * 64];
__device__ __align__(16) float g_p2[2 * 200 * 64];
// h B-fragments: [side][wn][lane][8 x uint4]  (words 0..15 = hi, 16..31 = lo)
__device__ __align__(16) uint4 g_frag[2][4][32][8];

// ================= helpers =================
__device__ __forceinline__ uint32_t smem_u32(const void* p) {
    uint32_t a;
    asm("{ .reg .u64 t; cvta.to.shared.u64 t, %1; cvt.u32.u64 %0, t; }" : "=r"(a) : "l"(p));
    return a;
}
__device__ __forceinline__ void ldsm_x4(uint32_t* r, uint32_t addr) {
    asm volatile("ldmatrix.sync.aligned.m8n8.x4.shared.b16 {%0,%1,%2,%3}, [%4];"
        : "=r"(r[0]), "=r"(r[1]), "=r"(r[2]), "=r"(r[3]) : "r"(addr));
}
__device__ __forceinline__ void ldsm_x2(uint32_t* r, uint32_t addr) {
    asm volatile("ldmatrix.sync.aligned.m8n8.x2.shared.b16 {%0,%1}, [%2];"
        : "=r"(r[0]), "=r"(r[1]) : "r"(addr));
}
__device__ __forceinline__ void mma_bf16(float* d, const uint32_t* a, const uint32_t* b) {
    asm volatile("mma.sync.aligned.m16n8k16.row.col.f32.bf16.bf16.f32 "
        "{%0,%1,%2,%3}, {%4,%5,%6,%7}, {%8,%9}, {%0,%1,%2,%3};"
        : "+f"(d[0]), "+f"(d[1]), "+f"(d[2]), "+f"(d[3])
        : "r"(a[0]), "r"(a[1]), "r"(a[2]), "r"(a[3]), "r"(b[0]), "r"(b[1]));
}
// pack hi16 halves of (a,b) -> bf16x2 (truncating split)
__device__ __forceinline__ uint32_t prmt_hi(float a, float b) {
    uint32_t r;
    asm("prmt.b32 %0, %1, %2, 0x7632;"
        : "=r"(r) : "r"(__float_as_uint(a)), "r"(__float_as_uint(b)));
    return r;
}
// residual after truncating hi split, packed bf16x2
__device__ __forceinline__ uint32_t pack_lo_resid(float a, float b) {
    float la = a - __uint_as_float(__float_as_uint(a) & 0xffff0000u);
    float lb = b - __uint_as_float(__float_as_uint(b) & 0xffff0000u);
    uint32_t r;
    asm("cvt.rn.bf16x2.f32 %0, %1, %2;" : "=r"(r) : "f"(lb), "f"(la));
    return r;
}

// ================= hypernet (blocks 0,1: h + B-fragments) + z transpose (blocks 2..) ====
__global__ __launch_bounds__(256) void hyper_tr(
    const float* __restrict__ mu,
    const float* __restrict__ enW0, const float* __restrict__ enb0,
    const float* __restrict__ enW1, const float* __restrict__ enb1,
    const float* __restrict__ deW0, const float* __restrict__ deb0,
    const float* __restrict__ deW1, const float* __restrict__ deb1,
    const float* __restrict__ z)
{
    int tid = threadIdx.x;
    if (blockIdx.x >= 2) {
        int idx = (blockIdx.x - 2) * 256 + tid;
        if (idx < 2000 * 64) {
            int i = idx >> 6, b = idx & 63;
            g_zT[idx] = z[b * 2000 + i];
        }
        return;
    }
    const int side = blockIdx.x;
    const float* W0; const float* b0; const float* W1; const float* b1;
    if (side == 0) { W0 = enW0; b0 = enb0; W1 = enW1; b1 = enb1; }
    else           { W0 = deW0; b0 = deb0; W1 = deW1; b1 = deb1; }

    __shared__ float mus[256];
    __shared__ float h1[64][65];
    __shared__ __align__(16) __nv_bfloat16 hsH[64 * 72];
    __shared__ __align__(16) __nv_bfloat16 hsL[64 * 72];

    mus[tid] = mu[tid];
    __syncthreads();
    for (int idx = tid; idx < 4096; idx += 256) {
        int b = idx >> 6, o = idx & 63;
        float s = b0[o];
#pragma unroll
        for (int j = 0; j < 4; j++) s += mus[b * 4 + j] * W0[o * 4 + j];
        h1[b][o] = tanhf(s);
    }
    __syncthreads();
    for (int idx = tid; idx < 4096; idx += 256) {
        int b = idx >> 6, o = idx & 63;
        float s = b1[o];
#pragma unroll
        for (int k = 0; k < 64; k++) s += h1[b][k] * W1[o * 64 + k];
        float f = tanhf(s);
        __nv_bfloat16 hi = __float2bfloat16_rn(f);
        __nv_bfloat16 lo = __float2bfloat16_rn(f - __bfloat162float(hi));
        hsH[b * 72 + o] = hi;
        hsL[b * 72 + o] = lo;
    }
    __syncthreads();

    // warps 0..3: build B fragments exactly as hfc consumers would, store to gmem
    int wid = tid >> 5, lane = tid & 31;
    if (wid < 4) {
        const int wn = wid;
        const uint32_t smbH = smem_u32(hsH), smbL = smem_u32(hsL);
        uint32_t w_[32];
        int l2 = lane & 15, rr = l2 & 7, rs = l2 >> 3;
#pragma unroll
        for (int nt = 0; nt < 2; nt++) {
            int bb = wn * 16 + nt * 8 + rr;
#pragma unroll
            for (int ks = 0; ks < 4; ks++) {
                uint32_t o_ = (uint32_t)(bb * 144 + ks * 32 + rs * 16);
                uint32_t th[2], tl[2];
                ldsm_x2(th, smbH + o_);
                ldsm_x2(tl, smbL + o_);
                w_[nt * 8 + ks * 2 + 0] = th[0];
                w_[nt * 8 + ks * 2 + 1] = th[1];
                w_[16 + nt * 8 + ks * 2 + 0] = tl[0];
                w_[16 + nt * 8 + ks * 2 + 1] = tl[1];
            }
        }
#pragma unroll
        for (int j = 0; j < 8; j++)
            g_frag[side][wn][lane][j] = make_uint4(w_[4*j], w_[4*j+1], w_[4*j+2], w_[4*j+3]);
    }
}

// ================= split reduce (+opt tanh, +opt row-major copy) =================
__global__ void reduce_kernel(const float* __restrict__ part, float* __restrict__ outT,
                              float* __restrict__ out, int ostride, int n, int s, int do_tanh)
{
    int i = blockIdx.x * 256 + threadIdx.x;
    if (i < n) {
        float v = 0.f;
        for (int j = 0; j < s; j++) v += part[(long)j * n + i];
        if (do_tanh) v = tanhf(v);
        if (outT) outT[i] = v;
        if (out) { int c = i >> 6, b = i & 63; out[b * ostride + c] = v; }
    }
}

// ================= fused hyper-FC: team-staged HMMA =================
// Block = 256 thr = 2 teams x 4 warps. Team owns channel cc = grp*2+team in K-split.
// Per 16-row tile: D[j,b] = Wrows @ h^T (3-term bf16 split, fp32 acc);
//                  acc[b] += (D[j,b] + b2[j]) * x'[j,b]   (x'[ni]=1 folds layer bias).
__global__ void __launch_bounds__(256) hfc(
    const float* __restrict__ W2, const float* __restrict__ b2,
    const float* __restrict__ xT, const uint4* __restrict__ hfrag,
    float* __restrict__ part_out,
    float* __restrict__ outT, float* __restrict__ out, int ostride, int do_tanh,
    int ni, int no, long off, int nsplit)
{
    __shared__ __align__(16) char wt[2][2 * 4608];   // team, stage x {hi(2304), lo(2304)}
    __shared__ float b2s[2][2][16];

    const int tid = threadIdx.x, lane = tid & 31, wid = tid >> 5;
    const int team = wid >> 2, wn = wid & 3, tt = tid & 127;
    const int grp = blockIdx.x / nsplit, split = blockIdx.x % nsplit;
    const int cc = grp * 2 + team;
    const int K1 = ni + 1;
    const int ilen = (K1 + nsplit - 1) / nsplit;
    const int ibeg = split * ilen;
    const int iend = min(ibeg + ilen, K1);
    const int ntiles = (iend - ibeg + 15) >> 4;

    // ---- B fragments: 8 coalesced LDG.128, no smem, no block sync ----
    uint32_t bh[2][4][2], bl[2][4][2];
    {
        const uint4* fp = hfrag + (wn * 32 + lane) * 8;
        uint32_t w_[32];
#pragma unroll
        for (int j = 0; j < 8; j++) {
            uint4 v = fp[j];
            w_[4*j] = v.x; w_[4*j+1] = v.y; w_[4*j+2] = v.z; w_[4*j+3] = v.w;
        }
#pragma unroll
        for (int nt = 0; nt < 2; nt++)
#pragma unroll
        for (int ks = 0; ks < 4; ks++)
#pragma unroll
        for (int r = 0; r < 2; r++) {
            bh[nt][ks][r] = w_[nt * 8 + ks * 2 + r];
            bl[nt][ks][r] = w_[16 + nt * 8 + ks * 2 + r];
        }
    }

    const long wbase = off + (long)cc * ni;
    const long brow  = off + (long)ni * no + cc;
    const int sr = tt >> 3, sq = tt & 7;            // stage mapping: row 0..15, col8 0..7
    const uint32_t wtb = smem_u32(wt[team]);
    const int barid = 1 + team;

    float4 pwa, pwb; float pb2;
    auto ldg_tile = [&](int i0) {
        int gi = i0 + sr;
        bool valid = gi < iend;
        long row = (gi < ni) ? (wbase + gi) : brow;
        const float4 f40 = make_float4(0.f, 0.f, 0.f, 0.f);
        pwa = valid ? *(const float4*)(W2 + row * 64 + sq * 8)     : f40;
        pwb = valid ? *(const float4*)(W2 + row * 64 + sq * 8 + 4) : f40;
        pb2 = (valid && sq == 0) ? b2[row] : 0.f;
    };
    auto sts_tile = [&](int sbuf) {
        char* ph = wt[team] + sbuf * 4608 + sr * 144 + sq * 16;
        uint4 H, L;
        H.x = prmt_hi(pwa.x, pwa.y); H.y = prmt_hi(pwa.z, pwa.w);
        H.z = prmt_hi(pwb.x, pwb.y); H.w = prmt_hi(pwb.z, pwb.w);
        L.x = pack_lo_resid(pwa.x, pwa.y); L.y = pack_lo_resid(pwa.z, pwa.w);
        L.z = pack_lo_resid(pwb.x, pwb.y); L.w = pack_lo_resid(pwb.z, pwb.w);
        *(uint4*)ph = H;
        *(uint4*)(ph + 2304) = L;
        if (sq == 0) b2s[team][sbuf][sr] = pb2;
    };

    ldg_tile(ibeg);
    sts_tile(0);

    float acc[4] = {0.f, 0.f, 0.f, 0.f};
    const float2 z2 = make_float2(0.f, 0.f);
    int buf = 0;

    for (int mt = 0; mt < ntiles; ++mt) {
        if (mt + 1 < ntiles) ldg_tile(ibeg + (mt + 1) * 16);   // prefetch into regs
        asm volatile("bar.sync %0, 128;" :: "r"(barid) : "memory");

        // ---- x loads ----
        const int g0 = ibeg + mt * 16 + (lane >> 2);
        const int g1 = g0 + 8;
        const bool v0 = g0 < iend, v1 = g1 < iend;
        float2 x0[2], x1[2];
#pragma unroll
        for (int nt = 0; nt < 2; nt++) {
            int col = wn * 16 + nt * 8 + (lane & 3) * 2;
            x0[nt] = v0 ? (g0 < ni ? *(const float2*)(xT + (long)g0 * 64 + col) : make_float2(1.f, 1.f)) : z2;
            x1[nt] = v1 ? (g1 < ni ? *(const float2*)(xT + (long)g1 * 64 + col) : make_float2(1.f, 1.f)) : z2;
        }

        // ---- A fragments via ldmatrix ----
        uint32_t aH[4][4], aL[4][4];
        {
            int lrow = (lane & 7) + ((lane >> 3) & 1) * 8;
            int kh = lane >> 4;
            uint32_t base = wtb + buf * 4608 + (uint32_t)(lrow * 144 + kh * 16);
#pragma unroll
            for (int ks = 0; ks < 4; ks++) {
                ldsm_x4(aH[ks], base + ks * 32);
                ldsm_x4(aL[ks], base + 2304 + ks * 32);
            }
        }

        // ---- MMA (3-term split) ----
        float d[2][4] = {{0.f,0.f,0.f,0.f},{0.f,0.f,0.f,0.f}};
#pragma unroll
        for (int ks = 0; ks < 4; ks++) {
#pragma unroll
            for (int nt = 0; nt < 2; nt++) {
                mma_bf16(d[nt], aH[ks], bh[nt][ks]);
                mma_bf16(d[nt], aH[ks], bl[nt][ks]);
                mma_bf16(d[nt], aL[ks], bh[nt][ks]);
            }
        }

        // ---- fold with bias + x ----
        const float bb0 = b2s[team][buf][lane >> 2];
        const float bb1 = b2s[team][buf][(lane >> 2) + 8];
#pragma unroll
        for (int nt = 0; nt < 2; nt++) {
            acc[nt * 2 + 0] += (d[nt][0] + bb0) * x0[nt].x + (d[nt][2] + bb1) * x1[nt].x;
            acc[nt * 2 + 1] += (d[nt][1] + bb0) * x0[nt].y + (d[nt][3] + bb1) * x1[nt].y;
        }

        if (mt + 1 < ntiles) sts_tile(buf ^ 1);
        buf ^= 1;
    }

    // ---- reduce over j-groups (lane bits 2..4) and write ----
#pragma unroll
    for (int e = 0; e < 4; e++) {
        acc[e] += __shfl_xor_sync(0xffffffffu, acc[e], 4);
        acc[e] += __shfl_xor_sync(0xffffffffu, acc[e], 8);
        acc[e] += __shfl_xor_sync(0xffffffffu, acc[e], 16);
    }
    if (lane < 4) {
#pragma unroll
        for (int nt = 0; nt < 2; nt++)
#pragma unroll
        for (int e2 = 0; e2 < 2; e2++) {
            int col = wn * 16 + nt * 8 + lane * 2 + e2;
            float v = acc[nt * 2 + e2];
            if (part_out) {
                part_out[(long)split * (no * 64) + (long)cc * 64 + col] = v;
            } else {
                if (do_tanh) v = tanhf(v);
                if (outT) outT[(long)cc * 64 + col] = v;
                if (out)  out[(long)col * ostride + cc] = v;
            }
        }
    }
}

extern "C" void kernel_launch(void* const* d_in, const int* in_sizes, int n_in,
                              void* d_out, int out_size)
{
    const float* z    = (const float*)d_in[0];
    const float* mu   = (const float*)d_in[1];
    const float* enW0 = (const float*)d_in[2];
    const float* enb0 = (const float*)d_in[3];
    const float* enW1 = (const float*)d_in[4];
    const float* enb1 = (const float*)d_in[5];
    const float* enW2 = (const float*)d_in[6];
    const float* enb2 = (const float*)d_in[7];
    const float* deW0 = (const float*)d_in[8];
    const float* deb0 = (const float*)d_in[9];
    const float* deW1 = (const float*)d_in[10];
    const float* deb1 = (const float*)d_in[11];
    const float* deW2 = (const float*)d_in[12];
    const float* deb2 = (const float*)d_in[13];
    float* out = (float*)d_out;

    float *zT, *b1T, *b2T, *latT, *b3T, *b4T, *p1, *p2;
    uint4* frag;
    cudaGetSymbolAddress((void**)&zT,   g_zT);
    cudaGetSymbolAddress((void**)&b1T,  g_b1T);
    cudaGetSymbolAddress((void**)&b2T,  g_b2T);
    cudaGetSymbolAddress((void**)&latT, g_latT);
    cudaGetSymbolAddress((void**)&b3T,  g_b3T);
    cudaGetSymbolAddress((void**)&b4T,  g_b4T);
    cudaGetSymbolAddress((void**)&p1,   g_p1);
    cudaGetSymbolAddress((void**)&p2,   g_p2);
    cudaGetSymbolAddress((void**)&frag, g_frag);

    const uint4* fragEn = frag;
    const uint4* fragDe = frag + 4 * 32 * 8;

    // hypernet hidden states (+B fragments) + z transpose
    hyper_tr<<<502, 256>>>(mu, enW0, enb0, enW1, enb1, deW0, deb0, deW1, deb1, z);

    // encoder L0: 2000->200 linear, 3 K-splits (grid 300)
    hfc<<<300, 256>>>(enW2, enb2, zT, fragEn, p1, nullptr, nullptr, 0, 0,
                      2000, 200, 0L, 3);
    reduce_kernel<<<50, 256>>>(p1, b1T, nullptr, 0, 12800, 3, 0);
    // encoder L1: 200->100, 2 splits (grid 100), tanh in reduce
    hfc<<<100, 256>>>(enW2, enb2, b1T, fragEn, p2, nullptr, nullptr, 0, 0,
                      200, 100, 400200L, 2);
    reduce_kernel<<<25, 256>>>(p2, b2T, nullptr, 0, 6400, 2, 1);
    // encoder L2: 100->10, 2 splits (grid 10); reduce -> latT + latent tail of d_out
    hfc<<<10, 256>>>(enW2, enb2, b2T, fragEn, p1, nullptr, nullptr, 0, 0,
                     100, 10, 420300L, 2);
    reduce_kernel<<<3, 256>>>(p1, latT, out + 128000, 10, 640, 2, 0);

    // decoder L0: 10->100 linear, direct transposed write (grid 50)
    hfc<<<50, 256>>>(deW2, deb2, latT, fragDe, nullptr, b3T, nullptr, 0, 0,
                     10, 100, 0L, 1);
    // decoder L1: 100->200, tanh, direct transposed write (grid 100)
    hfc<<<100, 256>>>(deW2, deb2, b3T, fragDe, nullptr, b4T, nullptr, 0, 1,
                      100, 200, 1100L, 1);
    // decoder L2: 200->2000 linear, straight to d_out row-major (grid 1000)
    hfc<<<1000, 256>>>(deW2, deb2, b4T, fragDe, nullptr, nullptr, out, 2000, 0,
                       200, 2000, 21300L, 1);
}